// round 15
// baseline (speedup 1.0000x reference)
#include <cuda_runtime.h>
#include <cstdint>

#define NPTS 50000
#define DIM  128
#define W4   (DIM / 4)
#define TANCH 1024
#define KNEG 10
#define GAMMA 1.0f
#define QSCALE 20.0f

#define MA 16                  // anchors per CTA (one m16 tile)
#define NSEG 8                 // mining segments
#define NSEGR 8                // refine segments (1 pool each)
#define TILE_N 128
#define TILES_PER_SEG 49
#define SEG_LEN (TILES_PER_SEG * TILE_N)   // 6272
#define N_PAD (NSEG * SEG_LEN)             // 50176
#define STAGES 3

#define NSAMP 1024
#define KTAU 12
#define PCAP 192

// ---------------- static scratch ----------------
__device__ uint32_t g_Qrow[2][N_PAD][W4];
__device__ int g_sumb2[2][N_PAD];
__device__ int g_tau[2][TANCH];
__device__ int g_pool[2][TANCH][NSEG][PCAP];
__device__ int g_cnt[2][TANCH][NSEG];
__device__ float g_segd[2][TANCH][NSEGR][KNEG];
__device__ int   g_segi[2][TANCH][NSEGR][KNEG];
__device__ float g_partial[2 * TANCH];

// ---------------- helpers ----------------
__device__ __forceinline__ int dp4a(int acc, uint32_t a, uint32_t b) {
    int r;
    asm("dp4a.s32.s32 %0, %1, %2, %3;" : "=r"(r) : "r"(a), "r"(b), "r"(acc));
    return r;
}
__device__ __forceinline__ void mma_s8(int* c, const uint32_t* a, uint32_t b0, uint32_t b1) {
    asm volatile(
        "mma.sync.aligned.m16n8k32.row.col.s32.s8.s8.s32 "
        "{%0,%1,%2,%3},{%4,%5,%6,%7},{%8,%9},{%0,%1,%2,%3};"
        : "+r"(c[0]), "+r"(c[1]), "+r"(c[2]), "+r"(c[3])
        : "r"(a[0]), "r"(a[1]), "r"(a[2]), "r"(a[3]), "r"(b0), "r"(b1));
}
__device__ __forceinline__ int quants(float v) {
    return min(127, max(-127, __float2int_rn(v * QSCALE)));
}
__device__ __forceinline__ uint32_t pack4(int q0, int q1, int q2, int q3) {
    return (uint32_t)(q0 & 0xFF) | ((uint32_t)(q1 & 0xFF) << 8) |
           ((uint32_t)(q2 & 0xFF) << 16) | ((uint32_t)(q3 & 0xFF) << 24);
}
__device__ __forceinline__ uint32_t qword(const float* p) {
    float4 v = *(const float4*)p;
    return pack4(quants(v.x), quants(v.y), quants(v.z), quants(v.w));
}
__device__ __forceinline__ void cp_async16(uint32_t s, const void* g) {
    asm volatile("cp.async.cg.shared.global [%0], [%1], 16;\n" :: "r"(s), "l"(g));
}
__device__ __forceinline__ void cp_commit() { asm volatile("cp.async.commit_group;\n"); }
template <int N> __device__ __forceinline__ void cp_wait() {
    asm volatile("cp.async.wait_group %0;\n" :: "n"(N));
}
__device__ __forceinline__ float warp_sum(float v) {
    #pragma unroll
    for (int o = 16; o > 0; o >>= 1) v += __shfl_xor_sync(0xffffffffu, v, o);
    return v;
}
__device__ __forceinline__ int warp_min(int v) {
    #pragma unroll
    for (int o = 16; o > 0; o >>= 1) v = min(v, __shfl_xor_sync(0xffffffffu, v, o));
    return v;
}

// ---------------- kernel 1: quantize + pack + sumsq + zero counters ----------------
__global__ void quant_kernel(const float* __restrict__ out1,
                             const float* __restrict__ out2) {
    if (blockIdx.z == 0 && blockIdx.x < 64)
        ((int*)g_cnt)[blockIdx.x * 256 + threadIdx.x] = 0;

    const float* src = (blockIdx.z == 0) ? out1 : out2;
    const int warpId = threadIdx.x >> 5;
    const int lane = threadIdx.x & 31;
    const int rowBase = blockIdx.x * 64 + warpId * 8;
    #pragma unroll
    for (int r = 0; r < 8; ++r) {
        int n = rowBase + r;
        if (n < NPTS) {
            float4 v = *(const float4*)(src + n * DIM + 4 * lane);
            int q0 = quants(v.x), q1 = quants(v.y), q2 = quants(v.z), q3 = quants(v.w);
            g_Qrow[blockIdx.z][n][lane] = pack4(q0, q1, q2, q3);
            int tot = q0 * q0 + q1 * q1 + q2 * q2 + q3 * q3;
            #pragma unroll
            for (int o = 16; o > 0; o >>= 1) tot += __shfl_xor_sync(0xffffffffu, tot, o);
            if (lane == 0) g_sumb2[blockIdx.z][n] = tot;
        } else {
            g_Qrow[blockIdx.z][n][lane] = 0;
            if (lane == 0) g_sumb2[blockIdx.z][n] = 0x20000000;
        }
    }
}

// ---------------- kernel 2: tau threshold (12th smallest of 1024 samples) ----------------
__global__ __launch_bounds__(256)
void tau_kernel(const float* __restrict__ out1, const float* __restrict__ out2,
                const int* __restrict__ anchor1, const int* __restrict__ anchor2) {
    __shared__ uint32_t A_s[8][W4];
    const int warpId = threadIdx.x >> 5;
    const int lane = threadIdx.x & 31;
    const int g = blockIdx.x * 8 + warpId;
    const int dir = g >> 10;
    const int tt = g & 1023;
    const int bsel = (dir == 0) ? 1 : 0;
    const float* Arows = (dir == 0) ? out1 : out2;
    const int* anch = (dir == 0) ? anchor1 : anchor2;

    A_s[warpId][lane] = qword(Arows + anch[tt] * DIM + 4 * lane);
    __syncwarp();

    int kd[KTAU];
    #pragma unroll
    for (int k = 0; k < KTAU; ++k) kd[k] = 0x7fffffff;

    const uint32_t* A = A_s[warpId];
    for (int i = 0; i < NSAMP / 32; ++i) {
        int n = i * 32 + lane;
        const uint4* rp = (const uint4*)&g_Qrow[bsel][n][0];
        int dot = 0;
        #pragma unroll
        for (int w8 = 0; w8 < 8; ++w8) {
            uint4 b = rp[w8];
            uint4 a = *(const uint4*)&A[w8 * 4];
            dot = dp4a(dot, a.x, b.x);
            dot = dp4a(dot, a.y, b.y);
            dot = dp4a(dot, a.z, b.z);
            dot = dp4a(dot, a.w, b.w);
        }
        int key = g_sumb2[bsel][n] - 2 * dot;
        if (key < kd[KTAU - 1]) {
            #pragma unroll
            for (int j = KTAU - 1; j > 0; --j)
                kd[j] = min(kd[j], max(kd[j - 1], key));
            kd[0] = min(kd[0], key);
        }
    }

    int tauv = 0x7fffffff;
    #pragma unroll
    for (int r = 0; r < KTAU; ++r) {
        int gm = warp_min(kd[0]);
        if (kd[0] == gm) {
            #pragma unroll
            for (int j = 0; j < KTAU - 1; ++j) kd[j] = kd[j + 1];
            kd[KTAU - 1] = 0x7fffffff;
        }
        tauv = gm;
    }
    if (lane == 0) g_tau[dir][tt] = tauv;
}

// ---------------- kernel 3: IMMA mining (protected R12 win) ----------------
__global__ __launch_bounds__(256, 3)
void mine_mma_kernel(const float* __restrict__ out1, const float* __restrict__ out2,
                     const int* __restrict__ anchor1, const int* __restrict__ anchor2) {
    __shared__ uint32_t sB[STAGES][TILE_N][32];    // 48 KB, XOR-swizzled
    __shared__ int scnt[MA];

    const int dir = blockIdx.z;
    const int bsel = (dir == 0) ? 1 : 0;
    const int seg = blockIdx.y;
    const int tBase = blockIdx.x * MA;
    const float* Arows = (dir == 0) ? out1 : out2;
    const int*   anch  = (dir == 0) ? anchor1 : anchor2;

    const int tid = threadIdx.x;
    const int warpId = tid >> 5;
    const int lane = tid & 31;
    const int gid = lane >> 2;
    const int tig = lane & 3;
    const int segStart = seg * SEG_LEN;

    uint32_t afr[4][4];
    {
        const float* rA = Arows + anch[tBase + gid] * DIM;
        const float* rB = Arows + anch[tBase + gid + 8] * DIM;
        #pragma unroll
        for (int ks = 0; ks < 4; ++ks) {
            afr[ks][0] = qword(rA + 4 * (ks * 8 + tig));
            afr[ks][1] = qword(rB + 4 * (ks * 8 + tig));
            afr[ks][2] = qword(rA + 4 * (ks * 8 + tig + 4));
            afr[ks][3] = qword(rB + 4 * (ks * 8 + tig + 4));
        }
    }
    const int tau0 = g_tau[dir][tBase + gid];
    const int tau1 = g_tau[dir][tBase + gid + 8];
    if (tid < MA) scnt[tid] = 0;
    __syncthreads();

    auto load_tile = [&](int s, int t) {
        uint32_t sb = (uint32_t)__cvta_generic_to_shared(&sB[s][0][0]);
        const int n0 = segStart + t * TILE_N;
        #pragma unroll
        for (int i = 0; i < 4; ++i) {
            int id = tid + 256 * i;
            int row = id >> 3;
            int cw = id & 7;
            const void* gp = (const char*)&g_Qrow[bsel][n0 + row][0] + cw * 16;
            uint32_t sw = (uint32_t)((cw * 16) ^ ((row & 7) * 16));
            cp_async16(sb + (uint32_t)(row * 128) + sw, gp);
        }
        cp_commit();
    };

    load_tile(0, 0);
    load_tile(1, 1);

    for (int t = 0; t < TILES_PER_SEG; ++t) {
        cp_wait<1>();
        __syncthreads();
        if (t + 2 < TILES_PER_SEG) load_tile((t + 2) % STAGES, t + 2);

        const uint32_t (*B)[32] = sB[t % STAGES];
        const int n0 = segStart + t * TILE_N;
        const int nw = warpId * 16;

        int c0[4] = {0, 0, 0, 0};
        int c1[4] = {0, 0, 0, 0};
        #pragma unroll
        for (int ks = 0; ks < 4; ++ks) {
            uint32_t b00 = B[nw + gid][(ks * 8 + tig) ^ (gid * 4)];
            uint32_t b01 = B[nw + gid][(ks * 8 + tig + 4) ^ (gid * 4)];
            uint32_t b10 = B[nw + 8 + gid][(ks * 8 + tig) ^ (gid * 4)];
            uint32_t b11 = B[nw + 8 + gid][(ks * 8 + tig + 4) ^ (gid * 4)];
            mma_s8(c0, afr[ks], b00, b01);
            mma_s8(c1, afr[ks], b10, b11);
        }

        #pragma unroll
        for (int nt = 0; nt < 2; ++nt) {
            const int* c = nt ? c1 : c0;
            const int ncol = n0 + nw + nt * 8 + tig * 2;
            int2 s2 = *(const int2*)&g_sumb2[bsel][ncol];
            int k00 = s2.x - 2 * c[0];
            int k01 = s2.y - 2 * c[1];
            int k02 = s2.x - 2 * c[2];
            int k03 = s2.y - 2 * c[3];
            if (k00 < tau0) { int p = atomicAdd(&scnt[gid], 1);     if (p < PCAP) g_pool[dir][tBase + gid][seg][p] = ncol; }
            if (k01 < tau0) { int p = atomicAdd(&scnt[gid], 1);     if (p < PCAP) g_pool[dir][tBase + gid][seg][p] = ncol + 1; }
            if (k02 < tau1) { int p = atomicAdd(&scnt[gid + 8], 1); if (p < PCAP) g_pool[dir][tBase + gid + 8][seg][p] = ncol; }
            if (k03 < tau1) { int p = atomicAdd(&scnt[gid + 8], 1); if (p < PCAP) g_pool[dir][tBase + gid + 8][seg][p] = ncol + 1; }
        }
    }

    __syncthreads();
    if (tid < MA)
        g_cnt[dir][tBase + tid][seg] = min(scnt[tid], PCAP);
}

// ---------------- kernel 4: refine — per-leader local top-10, end merge ----------------
__global__ __launch_bounds__(256)
void refine_seg_kernel(const float* __restrict__ out1, const float* __restrict__ out2,
                       const int* __restrict__ anchor1, const int* __restrict__ anchor2) {
    const int warpId = threadIdx.x >> 5;
    const int lane = threadIdx.x & 31;
    const int sw = lane >> 3;
    const int sl = lane & 7;
    const int gid = blockIdx.x * 8 + warpId;      // 16384 warps
    const int seg = gid & 7;
    const int tt = (gid >> 3) & 1023;
    const int dir = gid >> 13;

    const float* Arows = (dir == 0) ? out1 : out2;
    const int* anch = (dir == 0) ? anchor1 : anchor2;
    const float* G = (dir == 0) ? out2 : out1;

    // anchor fragment in registers (loop-invariant per lane)
    float4 av[4];
    {
        const float4* src = (const float4*)(Arows + anch[tt] * DIM);
        #pragma unroll
        for (int j = 0; j < 4; ++j) av[j] = src[sl + 8 * j];
    }

    const int total = min(g_cnt[dir][tt][seg], PCAP);
    const int* pool = &g_pool[dir][tt][seg][0];

    // local top-10 (meaningful only on leader lanes sl==0)
    float kd[KNEG]; int ki[KNEG];
    #pragma unroll
    for (int k = 0; k < KNEG; ++k) { kd[k] = 3.0e38f; ki[k] = 0x7fffffff; }

    auto load_batch = [&](int base, float4* v, int& idx) {
        int k = base + sw;
        idx = -1;
        if (k < total) {
            idx = min(pool[k], NPTS - 1);
            const float4* nr = (const float4*)(G + idx * DIM);
            #pragma unroll
            for (int j = 0; j < 4; ++j) v[j] = nr[sl + 8 * j];
        }
    };

    float4 cv[4];
    int cidx;
    load_batch(0, cv, cidx);

    for (int base = 0; base < total; base += 4) {
        float4 nv[4];
        int nidx = -1;
        if (base + 4 < total) load_batch(base + 4, nv, nidx);

        float p = 0.0f;
        if (cidx >= 0) {
            #pragma unroll
            for (int j = 0; j < 4; ++j) {
                float4 a = av[j];
                float4 b = cv[j];
                p += fabsf(a.x - b.x) + fabsf(a.y - b.y) +
                     fabsf(a.z - b.z) + fabsf(a.w - b.w);
            }
        }
        p += __shfl_xor_sync(0xffffffffu, p, 4);
        p += __shfl_xor_sync(0xffffffffu, p, 2);
        p += __shfl_xor_sync(0xffffffffu, p, 1);

        // leader-local insert (no cross-lane traffic)
        if (sl == 0 && cidx >= 0) {
            bool better = (p < kd[KNEG - 1]) ||
                          (p == kd[KNEG - 1] && cidx < ki[KNEG - 1]);
            if (better) {
                int pos = KNEG - 1;
                #pragma unroll
                for (int q = KNEG - 2; q >= 0; --q)
                    if (kd[q] > p || (kd[q] == p && ki[q] > cidx)) pos = q;
                #pragma unroll
                for (int q = KNEG - 1; q > 0; --q)
                    if (q > pos) { kd[q] = kd[q - 1]; ki[q] = ki[q - 1]; }
                kd[pos] = p; ki[pos] = cidx;
            }
        }

        cidx = nidx;
        #pragma unroll
        for (int j = 0; j < 4; ++j) cv[j] = nv[j];
    }

    // merge leaders 8, 16, 24 into lane 0's top-10
    #pragma unroll
    for (int srcw = 1; srcw < 4; ++srcw) {
        #pragma unroll
        for (int k = 0; k < KNEG; ++k) {
            float d = __shfl_sync(0xffffffffu, kd[k], srcw * 8);
            int  ix = __shfl_sync(0xffffffffu, ki[k], srcw * 8);
            if (lane == 0) {
                bool better = (d < kd[KNEG - 1]) ||
                              (d == kd[KNEG - 1] && ix < ki[KNEG - 1]);
                if (better) {
                    int pos = KNEG - 1;
                    #pragma unroll
                    for (int q = KNEG - 2; q >= 0; --q)
                        if (kd[q] > d || (kd[q] == d && ki[q] > ix)) pos = q;
                    #pragma unroll
                    for (int q = KNEG - 1; q > 0; --q)
                        if (q > pos) { kd[q] = kd[q - 1]; ki[q] = ki[q - 1]; }
                    kd[pos] = d; ki[pos] = ix;
                }
            }
        }
    }

    if (lane == 0) {
        #pragma unroll
        for (int k = 0; k < KNEG; ++k) {
            g_segd[dir][tt][seg][k] = kd[k];
            g_segi[dir][tt][seg][k] = ki[k];
        }
    }
}

// ---------------- kernel 5: merge segments + loss ----------------
__global__ __launch_bounds__(256)
void merge_loss_kernel(const float* __restrict__ out1, const float* __restrict__ out2,
                       const int* __restrict__ anchor1, const int* __restrict__ anchor2) {
    const int warpId = threadIdx.x >> 5;
    const int lane = threadIdx.x & 31;
    const int g = blockIdx.x * 8 + warpId;
    const int dir = g >> 10;
    const int tt = g & 1023;

    const float* r1 = out1 + anchor1[tt] * DIM;
    const float* r2 = out2 + anchor2[tt] * DIM;
    float A = 0.0f;
    #pragma unroll
    for (int j = 0; j < 4; ++j)
        A += fabsf(r1[lane + 32 * j] - r2[lane + 32 * j]);
    A = warp_sum(A);
    const float Dm = A + GAMMA;

    if (lane == 0) {
        float kd[KNEG]; int ki[KNEG];
        #pragma unroll
        for (int k = 0; k < KNEG; ++k) { kd[k] = 3.0e38f; ki[k] = 0x7fffffff; }
        for (int seg = 0; seg < NSEGR; ++seg) {
            #pragma unroll
            for (int k = 0; k < KNEG; ++k) {
                float d = g_segd[dir][tt][seg][k];
                int  ix = g_segi[dir][tt][seg][k];
                bool better = (d < kd[KNEG - 1]) ||
                              (d == kd[KNEG - 1] && ix < ki[KNEG - 1]);
                if (better) {
                    int pos = KNEG - 1;
                    #pragma unroll
                    for (int q = KNEG - 2; q >= 0; --q)
                        if (kd[q] > d || (kd[q] == d && ki[q] > ix)) pos = q;
                    #pragma unroll
                    for (int q = KNEG - 1; q > 0; --q)
                        if (q > pos) { kd[q] = kd[q - 1]; ki[q] = ki[q - 1]; }
                    kd[pos] = d; ki[pos] = ix;
                }
            }
        }
        float lsum = 0.0f;
        #pragma unroll
        for (int k = 0; k < KNEG; ++k) lsum += fmaxf(Dm - kd[k], 0.0f);
        g_partial[g] = lsum;
    }
}

// ---------------- kernel 6: deterministic reduction ----------------
__global__ void reduce_kernel(float* __restrict__ out) {
    __shared__ float sh[1024];
    int t = threadIdx.x;
    sh[t] = g_partial[t] + g_partial[t + 1024];
    __syncthreads();
    #pragma unroll
    for (int s = 512; s > 0; s >>= 1) {
        if (t < s) sh[t] += sh[t + s];
        __syncthreads();
    }
    if (t == 0) out[0] = sh[0] * (1.0f / (float)(TANCH * KNEG));
}

// ---------------- launch ----------------
extern "C" void kernel_launch(void* const* d_in, const int* in_sizes, int n_in,
                              void* d_out, int out_size) {
    const float* out1 = (const float*)d_in[0];
    const float* out2 = (const float*)d_in[1];
    const int* anchor1 = (const int*)d_in[2];
    const int* anchor2 = (const int*)d_in[3];
    float* out = (float*)d_out;

    quant_kernel<<<dim3(N_PAD / 64, 1, 2), 256>>>(out1, out2);                         // #1 (also zeros g_cnt)

    tau_kernel<<<2 * TANCH / 8, 256>>>(out1, out2, anchor1, anchor2);                  // #2

    mine_mma_kernel<<<dim3(TANCH / MA, NSEG, 2), 256>>>(out1, out2, anchor1, anchor2); // #3

    refine_seg_kernel<<<2 * TANCH * NSEGR / 8, 256>>>(out1, out2, anchor1, anchor2);   // #4 <- profiled

    merge_loss_kernel<<<2 * TANCH / 8, 256>>>(out1, out2, anchor1, anchor2);           // #5

    reduce_kernel<<<1, 1024>>>(out);                                                   // #6
}

// round 16
// speedup vs baseline: 1.1908x; 1.1908x over previous
#include <cuda_runtime.h>
#include <cstdint>

#define NPTS 50000
#define DIM  128
#define W4   (DIM / 4)
#define TANCH 1024
#define KNEG 10
#define GAMMA 1.0f
#define QSCALE 20.0f

#define MA 16                  // anchors per CTA (one m16 tile)
#define NSEG 8                 // mining segments
#define NSEGR 4                // refine segments (2 pools each)
#define TILE_N 128
#define TILES_PER_SEG 49
#define SEG_LEN (TILES_PER_SEG * TILE_N)   // 6272
#define N_PAD (NSEG * SEG_LEN)             // 50176
#define STAGES 3

#define NSAMP 1024
#define KTAU 12
#define PCAP 192

// ---------------- static scratch ----------------
__device__ uint32_t g_Qrow[2][N_PAD][W4];
__device__ int g_sumb2[2][N_PAD];
__device__ int g_tau[2][TANCH];
__device__ int g_pool[2][TANCH][NSEG][PCAP];
__device__ int g_cnt[2][TANCH][NSEG];
__device__ float g_segd[2][TANCH][NSEGR][KNEG];
__device__ int   g_segi[2][TANCH][NSEGR][KNEG];
__device__ float g_partial[2 * TANCH];

// ---------------- helpers ----------------
__device__ __forceinline__ int dp4a(int acc, uint32_t a, uint32_t b) {
    int r;
    asm("dp4a.s32.s32 %0, %1, %2, %3;" : "=r"(r) : "r"(a), "r"(b), "r"(acc));
    return r;
}
__device__ __forceinline__ void mma_s8(int* c, const uint32_t* a, uint32_t b0, uint32_t b1) {
    asm volatile(
        "mma.sync.aligned.m16n8k32.row.col.s32.s8.s8.s32 "
        "{%0,%1,%2,%3},{%4,%5,%6,%7},{%8,%9},{%0,%1,%2,%3};"
        : "+r"(c[0]), "+r"(c[1]), "+r"(c[2]), "+r"(c[3])
        : "r"(a[0]), "r"(a[1]), "r"(a[2]), "r"(a[3]), "r"(b0), "r"(b1));
}
__device__ __forceinline__ int quants(float v) {
    return min(127, max(-127, __float2int_rn(v * QSCALE)));
}
__device__ __forceinline__ uint32_t pack4(int q0, int q1, int q2, int q3) {
    return (uint32_t)(q0 & 0xFF) | ((uint32_t)(q1 & 0xFF) << 8) |
           ((uint32_t)(q2 & 0xFF) << 16) | ((uint32_t)(q3 & 0xFF) << 24);
}
__device__ __forceinline__ uint32_t qword(const float* p) {
    float4 v = *(const float4*)p;
    return pack4(quants(v.x), quants(v.y), quants(v.z), quants(v.w));
}
__device__ __forceinline__ void cp_async16(uint32_t s, const void* g) {
    asm volatile("cp.async.cg.shared.global [%0], [%1], 16;\n" :: "r"(s), "l"(g));
}
__device__ __forceinline__ void cp_commit() { asm volatile("cp.async.commit_group;\n"); }
template <int N> __device__ __forceinline__ void cp_wait() {
    asm volatile("cp.async.wait_group %0;\n" :: "n"(N));
}
__device__ __forceinline__ float warp_sum(float v) {
    #pragma unroll
    for (int o = 16; o > 0; o >>= 1) v += __shfl_xor_sync(0xffffffffu, v, o);
    return v;
}
__device__ __forceinline__ int warp_min(int v) {
    #pragma unroll
    for (int o = 16; o > 0; o >>= 1) v = min(v, __shfl_xor_sync(0xffffffffu, v, o));
    return v;
}

// ---------------- kernel 1: quantize + pack + sumsq + zero counters ----------------
__global__ void quant_kernel(const float* __restrict__ out1,
                             const float* __restrict__ out2) {
    if (blockIdx.z == 0 && blockIdx.x < 64)
        ((int*)g_cnt)[blockIdx.x * 256 + threadIdx.x] = 0;

    const float* src = (blockIdx.z == 0) ? out1 : out2;
    const int warpId = threadIdx.x >> 5;
    const int lane = threadIdx.x & 31;
    const int rowBase = blockIdx.x * 64 + warpId * 8;
    #pragma unroll
    for (int r = 0; r < 8; ++r) {
        int n = rowBase + r;
        if (n < NPTS) {
            float4 v = *(const float4*)(src + n * DIM + 4 * lane);
            int q0 = quants(v.x), q1 = quants(v.y), q2 = quants(v.z), q3 = quants(v.w);
            g_Qrow[blockIdx.z][n][lane] = pack4(q0, q1, q2, q3);
            int tot = q0 * q0 + q1 * q1 + q2 * q2 + q3 * q3;
            #pragma unroll
            for (int o = 16; o > 0; o >>= 1) tot += __shfl_xor_sync(0xffffffffu, tot, o);
            if (lane == 0) g_sumb2[blockIdx.z][n] = tot;
        } else {
            g_Qrow[blockIdx.z][n][lane] = 0;
            if (lane == 0) g_sumb2[blockIdx.z][n] = 0x20000000;
        }
    }
}

// ---------------- kernel 2: tau threshold (12th smallest of 1024 samples) ----------------
__global__ __launch_bounds__(256)
void tau_kernel(const float* __restrict__ out1, const float* __restrict__ out2,
                const int* __restrict__ anchor1, const int* __restrict__ anchor2) {
    __shared__ uint32_t A_s[8][W4];
    const int warpId = threadIdx.x >> 5;
    const int lane = threadIdx.x & 31;
    const int g = blockIdx.x * 8 + warpId;
    const int dir = g >> 10;
    const int tt = g & 1023;
    const int bsel = (dir == 0) ? 1 : 0;
    const float* Arows = (dir == 0) ? out1 : out2;
    const int* anch = (dir == 0) ? anchor1 : anchor2;

    A_s[warpId][lane] = qword(Arows + anch[tt] * DIM + 4 * lane);
    __syncwarp();

    int kd[KTAU];
    #pragma unroll
    for (int k = 0; k < KTAU; ++k) kd[k] = 0x7fffffff;

    const uint32_t* A = A_s[warpId];
    for (int i = 0; i < NSAMP / 32; ++i) {
        int n = i * 32 + lane;
        const uint4* rp = (const uint4*)&g_Qrow[bsel][n][0];
        int dot = 0;
        #pragma unroll
        for (int w8 = 0; w8 < 8; ++w8) {
            uint4 b = rp[w8];
            uint4 a = *(const uint4*)&A[w8 * 4];
            dot = dp4a(dot, a.x, b.x);
            dot = dp4a(dot, a.y, b.y);
            dot = dp4a(dot, a.z, b.z);
            dot = dp4a(dot, a.w, b.w);
        }
        int key = g_sumb2[bsel][n] - 2 * dot;
        if (key < kd[KTAU - 1]) {
            #pragma unroll
            for (int j = KTAU - 1; j > 0; --j)
                kd[j] = min(kd[j], max(kd[j - 1], key));
            kd[0] = min(kd[0], key);
        }
    }

    int tauv = 0x7fffffff;
    #pragma unroll
    for (int r = 0; r < KTAU; ++r) {
        int gm = warp_min(kd[0]);
        if (kd[0] == gm) {
            #pragma unroll
            for (int j = 0; j < KTAU - 1; ++j) kd[j] = kd[j + 1];
            kd[KTAU - 1] = 0x7fffffff;
        }
        tauv = gm;
    }
    if (lane == 0) g_tau[dir][tt] = tauv;
}

// ---------------- kernel 3: IMMA mining (protected R12 win) ----------------
__global__ __launch_bounds__(256, 3)
void mine_mma_kernel(const float* __restrict__ out1, const float* __restrict__ out2,
                     const int* __restrict__ anchor1, const int* __restrict__ anchor2) {
    __shared__ uint32_t sB[STAGES][TILE_N][32];    // 48 KB, XOR-swizzled
    __shared__ int scnt[MA];

    const int dir = blockIdx.z;
    const int bsel = (dir == 0) ? 1 : 0;
    const int seg = blockIdx.y;
    const int tBase = blockIdx.x * MA;
    const float* Arows = (dir == 0) ? out1 : out2;
    const int*   anch  = (dir == 0) ? anchor1 : anchor2;

    const int tid = threadIdx.x;
    const int warpId = tid >> 5;
    const int lane = tid & 31;
    const int gid = lane >> 2;
    const int tig = lane & 3;
    const int segStart = seg * SEG_LEN;

    uint32_t afr[4][4];
    {
        const float* rA = Arows + anch[tBase + gid] * DIM;
        const float* rB = Arows + anch[tBase + gid + 8] * DIM;
        #pragma unroll
        for (int ks = 0; ks < 4; ++ks) {
            afr[ks][0] = qword(rA + 4 * (ks * 8 + tig));
            afr[ks][1] = qword(rB + 4 * (ks * 8 + tig));
            afr[ks][2] = qword(rA + 4 * (ks * 8 + tig + 4));
            afr[ks][3] = qword(rB + 4 * (ks * 8 + tig + 4));
        }
    }
    const int tau0 = g_tau[dir][tBase + gid];
    const int tau1 = g_tau[dir][tBase + gid + 8];
    if (tid < MA) scnt[tid] = 0;
    __syncthreads();

    auto load_tile = [&](int s, int t) {
        uint32_t sb = (uint32_t)__cvta_generic_to_shared(&sB[s][0][0]);
        const int n0 = segStart + t * TILE_N;
        #pragma unroll
        for (int i = 0; i < 4; ++i) {
            int id = tid + 256 * i;
            int row = id >> 3;
            int cw = id & 7;
            const void* gp = (const char*)&g_Qrow[bsel][n0 + row][0] + cw * 16;
            uint32_t sw = (uint32_t)((cw * 16) ^ ((row & 7) * 16));
            cp_async16(sb + (uint32_t)(row * 128) + sw, gp);
        }
        cp_commit();
    };

    load_tile(0, 0);
    load_tile(1, 1);

    for (int t = 0; t < TILES_PER_SEG; ++t) {
        cp_wait<1>();
        __syncthreads();
        if (t + 2 < TILES_PER_SEG) load_tile((t + 2) % STAGES, t + 2);

        const uint32_t (*B)[32] = sB[t % STAGES];
        const int n0 = segStart + t * TILE_N;
        const int nw = warpId * 16;

        int c0[4] = {0, 0, 0, 0};
        int c1[4] = {0, 0, 0, 0};
        #pragma unroll
        for (int ks = 0; ks < 4; ++ks) {
            uint32_t b00 = B[nw + gid][(ks * 8 + tig) ^ (gid * 4)];
            uint32_t b01 = B[nw + gid][(ks * 8 + tig + 4) ^ (gid * 4)];
            uint32_t b10 = B[nw + 8 + gid][(ks * 8 + tig) ^ (gid * 4)];
            uint32_t b11 = B[nw + 8 + gid][(ks * 8 + tig + 4) ^ (gid * 4)];
            mma_s8(c0, afr[ks], b00, b01);
            mma_s8(c1, afr[ks], b10, b11);
        }

        #pragma unroll
        for (int nt = 0; nt < 2; ++nt) {
            const int* c = nt ? c1 : c0;
            const int ncol = n0 + nw + nt * 8 + tig * 2;
            int2 s2 = *(const int2*)&g_sumb2[bsel][ncol];
            int k00 = s2.x - 2 * c[0];
            int k01 = s2.y - 2 * c[1];
            int k02 = s2.x - 2 * c[2];
            int k03 = s2.y - 2 * c[3];
            if (k00 < tau0) { int p = atomicAdd(&scnt[gid], 1);     if (p < PCAP) g_pool[dir][tBase + gid][seg][p] = ncol; }
            if (k01 < tau0) { int p = atomicAdd(&scnt[gid], 1);     if (p < PCAP) g_pool[dir][tBase + gid][seg][p] = ncol + 1; }
            if (k02 < tau1) { int p = atomicAdd(&scnt[gid + 8], 1); if (p < PCAP) g_pool[dir][tBase + gid + 8][seg][p] = ncol; }
            if (k03 < tau1) { int p = atomicAdd(&scnt[gid + 8], 1); if (p < PCAP) g_pool[dir][tBase + gid + 8][seg][p] = ncol + 1; }
        }
    }

    __syncthreads();
    if (tid < MA)
        g_cnt[dir][tBase + tid][seg] = min(scnt[tid], PCAP);
}

// ---------------- kernel 4: refine — R14 structure + depth-3 prefetch ----------------
__global__ __launch_bounds__(256)
void refine_seg_kernel(const float* __restrict__ out1, const float* __restrict__ out2,
                       const int* __restrict__ anchor1, const int* __restrict__ anchor2) {
    const int warpId = threadIdx.x >> 5;
    const int lane = threadIdx.x & 31;
    const int sw = lane >> 3;
    const int sl = lane & 7;
    const int gid = blockIdx.x * 8 + warpId;      // 8192 warps
    const int rseg = gid & 3;
    const int tt = (gid >> 2) & 1023;
    const int dir = gid >> 12;

    const float* Arows = (dir == 0) ? out1 : out2;
    const int* anch = (dir == 0) ? anchor1 : anchor2;
    const float* G = (dir == 0) ? out2 : out1;

    // anchor fragment in registers (loop-invariant per lane)
    float4 av[4];
    {
        const float4* src = (const float4*)(Arows + anch[tt] * DIM);
        #pragma unroll
        for (int j = 0; j < 4; ++j) av[j] = src[sl + 8 * j];
    }

    const int cnt0 = min(g_cnt[dir][tt][rseg * 2], PCAP);
    const int cnt1 = min(g_cnt[dir][tt][rseg * 2 + 1], PCAP);
    const int total = cnt0 + cnt1;
    const int* pool0 = &g_pool[dir][tt][rseg * 2][0];
    const int* pool1 = &g_pool[dir][tt][rseg * 2 + 1][0];

    float kd[KNEG]; int ki[KNEG];
    #pragma unroll
    for (int k = 0; k < KNEG; ++k) { kd[k] = 3.0e38f; ki[k] = 0x7fffffff; }

    auto load_batch = [&](int base, float4* v, int& idx) {
        int k = base + sw;
        idx = -1;
        if (k < total) {
            int raw = (k < cnt0) ? pool0[k] : pool1[k - cnt0];
            idx = min(raw, NPTS - 1);
            const float4* nr = (const float4*)(G + idx * DIM);
            #pragma unroll
            for (int j = 0; j < 4; ++j) v[j] = nr[sl + 8 * j];
        }
    };

    // depth-3 pipeline: batches at base, base+4, base+8 in flight
    float4 v0[4], v1[4];
    int i0 = -1, i1 = -1;
    load_batch(0, v0, i0);
    if (total > 4) load_batch(4, v1, i1);

    for (int base = 0; base < total; base += 4) {
        float4 v2[4];
        int i2 = -1;
        if (base + 8 < total) load_batch(base + 8, v2, i2);

        float dsum = 3.0e38f;
        {
            float p = 0.0f;
            if (i0 >= 0) {
                #pragma unroll
                for (int j = 0; j < 4; ++j) {
                    float4 a = av[j];
                    float4 b = v0[j];
                    p += fabsf(a.x - b.x) + fabsf(a.y - b.y) +
                         fabsf(a.z - b.z) + fabsf(a.w - b.w);
                }
            }
            p += __shfl_xor_sync(0xffffffffu, p, 4);
            p += __shfl_xor_sync(0xffffffffu, p, 2);
            p += __shfl_xor_sync(0xffffffffu, p, 1);
            if (i0 >= 0) dsum = p;
        }

        float thr = __shfl_sync(0xffffffffu, kd[KNEG - 1], 0);
        int   thi = __shfl_sync(0xffffffffu, ki[KNEG - 1], 0);
        bool candp = (sl == 0) && (i0 >= 0) &&
                     (dsum < thr || (dsum == thr && i0 < thi));
        unsigned m = __ballot_sync(0xffffffffu, candp);
        while (m) {
            int src = __ffs(m) - 1; m &= m - 1;
            float d = __shfl_sync(0xffffffffu, dsum, src);
            int  ix = __shfl_sync(0xffffffffu, i0, src);
            if (lane == 0) {
                bool better = (d < kd[KNEG - 1]) ||
                              (d == kd[KNEG - 1] && ix < ki[KNEG - 1]);
                if (better) {
                    int pos = KNEG - 1;
                    #pragma unroll
                    for (int q = KNEG - 2; q >= 0; --q)
                        if (kd[q] > d || (kd[q] == d && ki[q] > ix)) pos = q;
                    #pragma unroll
                    for (int q = KNEG - 1; q > 0; --q)
                        if (q > pos) { kd[q] = kd[q - 1]; ki[q] = ki[q - 1]; }
                    kd[pos] = d; ki[pos] = ix;
                }
            }
        }

        i0 = i1; i1 = i2;
        #pragma unroll
        for (int j = 0; j < 4; ++j) { v0[j] = v1[j]; v1[j] = v2[j]; }
    }

    if (lane == 0) {
        #pragma unroll
        for (int k = 0; k < KNEG; ++k) {
            g_segd[dir][tt][rseg][k] = kd[k];
            g_segi[dir][tt][rseg][k] = ki[k];
        }
    }
}

// ---------------- kernel 5: merge segments + loss ----------------
__global__ __launch_bounds__(256)
void merge_loss_kernel(const float* __restrict__ out1, const float* __restrict__ out2,
                       const int* __restrict__ anchor1, const int* __restrict__ anchor2) {
    const int warpId = threadIdx.x >> 5;
    const int lane = threadIdx.x & 31;
    const int g = blockIdx.x * 8 + warpId;
    const int dir = g >> 10;
    const int tt = g & 1023;

    const float* r1 = out1 + anchor1[tt] * DIM;
    const float* r2 = out2 + anchor2[tt] * DIM;
    float A = 0.0f;
    #pragma unroll
    for (int j = 0; j < 4; ++j)
        A += fabsf(r1[lane + 32 * j] - r2[lane + 32 * j]);
    A = warp_sum(A);
    const float Dm = A + GAMMA;

    if (lane == 0) {
        float kd[KNEG]; int ki[KNEG];
        #pragma unroll
        for (int k = 0; k < KNEG; ++k) { kd[k] = 3.0e38f; ki[k] = 0x7fffffff; }
        for (int seg = 0; seg < NSEGR; ++seg) {
            #pragma unroll
            for (int k = 0; k < KNEG; ++k) {
                float d = g_segd[dir][tt][seg][k];
                int  ix = g_segi[dir][tt][seg][k];
                bool better = (d < kd[KNEG - 1]) ||
                              (d == kd[KNEG - 1] && ix < ki[KNEG - 1]);
                if (better) {
                    int pos = KNEG - 1;
                    #pragma unroll
                    for (int q = KNEG - 2; q >= 0; --q)
                        if (kd[q] > d || (kd[q] == d && ki[q] > ix)) pos = q;
                    #pragma unroll
                    for (int q = KNEG - 1; q > 0; --q)
                        if (q > pos) { kd[q] = kd[q - 1]; ki[q] = ki[q - 1]; }
                    kd[pos] = d; ki[pos] = ix;
                }
            }
        }
        float lsum = 0.0f;
        #pragma unroll
        for (int k = 0; k < KNEG; ++k) lsum += fmaxf(Dm - kd[k], 0.0f);
        g_partial[g] = lsum;
    }
}

// ---------------- kernel 6: deterministic reduction ----------------
__global__ void reduce_kernel(float* __restrict__ out) {
    __shared__ float sh[1024];
    int t = threadIdx.x;
    sh[t] = g_partial[t] + g_partial[t + 1024];
    __syncthreads();
    #pragma unroll
    for (int s = 512; s > 0; s >>= 1) {
        if (t < s) sh[t] += sh[t + s];
        __syncthreads();
    }
    if (t == 0) out[0] = sh[0] * (1.0f / (float)(TANCH * KNEG));
}

// ---------------- launch ----------------
extern "C" void kernel_launch(void* const* d_in, const int* in_sizes, int n_in,
                              void* d_out, int out_size) {
    const float* out1 = (const float*)d_in[0];
    const float* out2 = (const float*)d_in[1];
    const int* anchor1 = (const int*)d_in[2];
    const int* anchor2 = (const int*)d_in[3];
    float* out = (float*)d_out;

    quant_kernel<<<dim3(N_PAD / 64, 1, 2), 256>>>(out1, out2);                         // #1 (also zeros g_cnt)

    tau_kernel<<<2 * TANCH / 8, 256>>>(out1, out2, anchor1, anchor2);                  // #2

    mine_mma_kernel<<<dim3(TANCH / MA, NSEG, 2), 256>>>(out1, out2, anchor1, anchor2); // #3

    refine_seg_kernel<<<2 * TANCH * NSEGR / 8, 256>>>(out1, out2, anchor1, anchor2);   // #4 <- profiled

    merge_loss_kernel<<<2 * TANCH / 8, 256>>>(out1, out2, anchor1, anchor2);           // #5

    reduce_kernel<<<1, 1024>>>(out);                                                   // #6
}

// round 17
// speedup vs baseline: 1.2699x; 1.0665x over previous
#include <cuda_runtime.h>
#include <cstdint>

#define NPTS 50000
#define DIM  128
#define W4   (DIM / 4)
#define TANCH 1024
#define KNEG 10
#define GAMMA 1.0f
#define QSCALE 20.0f

#define MA 16                  // anchors per CTA (one m16 tile)
#define NSEG 8                 // mining segments
#define NSEGR 4                // refine segments (2 pools each)
#define TILE_N 256
#define TILES_PER_SEG 25
#define SEG_LEN (TILES_PER_SEG * TILE_N)   // 6400
#define N_PAD (NSEG * SEG_LEN)             // 51200

#define NSAMP 1024
#define KTAU 10
#define PCAP 192

#define MINE_SMEM (2 * TILE_N * 32 * 4)    // 65536 bytes dynamic

// ---------------- static scratch ----------------
__device__ uint32_t g_Qrow[2][N_PAD][W4];
__device__ int g_sumb2[2][N_PAD];
__device__ int g_tau[2][TANCH];
__device__ int g_pool[2][TANCH][NSEG][PCAP];
__device__ int g_cnt[2][TANCH][NSEG];
__device__ float g_segd[2][TANCH][NSEGR][KNEG];
__device__ int   g_segi[2][TANCH][NSEGR][KNEG];
__device__ float g_partial[2 * TANCH];

// ---------------- helpers ----------------
__device__ __forceinline__ int dp4a(int acc, uint32_t a, uint32_t b) {
    int r;
    asm("dp4a.s32.s32 %0, %1, %2, %3;" : "=r"(r) : "r"(a), "r"(b), "r"(acc));
    return r;
}
__device__ __forceinline__ void mma_s8(int* c, const uint32_t* a, uint32_t b0, uint32_t b1) {
    asm volatile(
        "mma.sync.aligned.m16n8k32.row.col.s32.s8.s8.s32 "
        "{%0,%1,%2,%3},{%4,%5,%6,%7},{%8,%9},{%0,%1,%2,%3};"
        : "+r"(c[0]), "+r"(c[1]), "+r"(c[2]), "+r"(c[3])
        : "r"(a[0]), "r"(a[1]), "r"(a[2]), "r"(a[3]), "r"(b0), "r"(b1));
}
__device__ __forceinline__ int quants(float v) {
    return min(127, max(-127, __float2int_rn(v * QSCALE)));
}
__device__ __forceinline__ uint32_t pack4(int q0, int q1, int q2, int q3) {
    return (uint32_t)(q0 & 0xFF) | ((uint32_t)(q1 & 0xFF) << 8) |
           ((uint32_t)(q2 & 0xFF) << 16) | ((uint32_t)(q3 & 0xFF) << 24);
}
__device__ __forceinline__ uint32_t qword(const float* p) {
    float4 v = *(const float4*)p;
    return pack4(quants(v.x), quants(v.y), quants(v.z), quants(v.w));
}
__device__ __forceinline__ void cp_async16(uint32_t s, const void* g) {
    asm volatile("cp.async.cg.shared.global [%0], [%1], 16;\n" :: "r"(s), "l"(g));
}
__device__ __forceinline__ void cp_commit() { asm volatile("cp.async.commit_group;\n"); }
template <int N> __device__ __forceinline__ void cp_wait() {
    asm volatile("cp.async.wait_group %0;\n" :: "n"(N));
}
__device__ __forceinline__ float warp_sum(float v) {
    #pragma unroll
    for (int o = 16; o > 0; o >>= 1) v += __shfl_xor_sync(0xffffffffu, v, o);
    return v;
}
__device__ __forceinline__ int warp_min(int v) {
    #pragma unroll
    for (int o = 16; o > 0; o >>= 1) v = min(v, __shfl_xor_sync(0xffffffffu, v, o));
    return v;
}

// ---------------- kernel 1: quantize + pack + sumsq + zero counters ----------------
__global__ void quant_kernel(const float* __restrict__ out1,
                             const float* __restrict__ out2) {
    if (blockIdx.z == 0 && blockIdx.x < 64)
        ((int*)g_cnt)[blockIdx.x * 256 + threadIdx.x] = 0;

    const float* src = (blockIdx.z == 0) ? out1 : out2;
    const int warpId = threadIdx.x >> 5;
    const int lane = threadIdx.x & 31;
    const int rowBase = blockIdx.x * 64 + warpId * 8;
    #pragma unroll
    for (int r = 0; r < 8; ++r) {
        int n = rowBase + r;
        if (n < NPTS) {
            float4 v = *(const float4*)(src + n * DIM + 4 * lane);
            int q0 = quants(v.x), q1 = quants(v.y), q2 = quants(v.z), q3 = quants(v.w);
            g_Qrow[blockIdx.z][n][lane] = pack4(q0, q1, q2, q3);
            int tot = q0 * q0 + q1 * q1 + q2 * q2 + q3 * q3;
            #pragma unroll
            for (int o = 16; o > 0; o >>= 1) tot += __shfl_xor_sync(0xffffffffu, tot, o);
            if (lane == 0) g_sumb2[blockIdx.z][n] = tot;
        } else {
            g_Qrow[blockIdx.z][n][lane] = 0;
            if (lane == 0) g_sumb2[blockIdx.z][n] = 0x20000000;
        }
    }
}

// ---------------- kernel 2: tau threshold (10th smallest of 1024 samples) ----------------
__global__ __launch_bounds__(256)
void tau_kernel(const float* __restrict__ out1, const float* __restrict__ out2,
                const int* __restrict__ anchor1, const int* __restrict__ anchor2) {
    __shared__ uint32_t A_s[8][W4];
    const int warpId = threadIdx.x >> 5;
    const int lane = threadIdx.x & 31;
    const int g = blockIdx.x * 8 + warpId;
    const int dir = g >> 10;
    const int tt = g & 1023;
    const int bsel = (dir == 0) ? 1 : 0;
    const float* Arows = (dir == 0) ? out1 : out2;
    const int* anch = (dir == 0) ? anchor1 : anchor2;

    A_s[warpId][lane] = qword(Arows + anch[tt] * DIM + 4 * lane);
    __syncwarp();

    int kd[KTAU];
    #pragma unroll
    for (int k = 0; k < KTAU; ++k) kd[k] = 0x7fffffff;

    const uint32_t* A = A_s[warpId];
    for (int i = 0; i < NSAMP / 32; ++i) {
        int n = i * 32 + lane;
        const uint4* rp = (const uint4*)&g_Qrow[bsel][n][0];
        int dot = 0;
        #pragma unroll
        for (int w8 = 0; w8 < 8; ++w8) {
            uint4 b = rp[w8];
            uint4 a = *(const uint4*)&A[w8 * 4];
            dot = dp4a(dot, a.x, b.x);
            dot = dp4a(dot, a.y, b.y);
            dot = dp4a(dot, a.z, b.z);
            dot = dp4a(dot, a.w, b.w);
        }
        int key = g_sumb2[bsel][n] - 2 * dot;
        if (key < kd[KTAU - 1]) {
            #pragma unroll
            for (int j = KTAU - 1; j > 0; --j)
                kd[j] = min(kd[j], max(kd[j - 1], key));
            kd[0] = min(kd[0], key);
        }
    }

    int tauv = 0x7fffffff;
    #pragma unroll
    for (int r = 0; r < KTAU; ++r) {
        int gm = warp_min(kd[0]);
        if (kd[0] == gm) {
            #pragma unroll
            for (int j = 0; j < KTAU - 1; ++j) kd[j] = kd[j + 1];
            kd[KTAU - 1] = 0x7fffffff;
        }
        tauv = gm;
    }
    if (lane == 0) g_tau[dir][tt] = tauv;
}

// ---------------- kernel 3: IMMA mining, TILE_N=256 double buffer ----------------
__global__ __launch_bounds__(256, 3)
void mine_mma_kernel(const float* __restrict__ out1, const float* __restrict__ out2,
                     const int* __restrict__ anchor1, const int* __restrict__ anchor2) {
    extern __shared__ uint32_t sBd[];              // [2][TILE_N][32] = 64 KB
    __shared__ int scnt[MA];

    const int dir = blockIdx.z;
    const int bsel = (dir == 0) ? 1 : 0;
    const int seg = blockIdx.y;
    const int tBase = blockIdx.x * MA;
    const float* Arows = (dir == 0) ? out1 : out2;
    const int*   anch  = (dir == 0) ? anchor1 : anchor2;

    const int tid = threadIdx.x;
    const int warpId = tid >> 5;
    const int lane = tid & 31;
    const int gid = lane >> 2;
    const int tig = lane & 3;
    const int segStart = seg * SEG_LEN;

    uint32_t afr[4][4];
    {
        const float* rA = Arows + anch[tBase + gid] * DIM;
        const float* rB = Arows + anch[tBase + gid + 8] * DIM;
        #pragma unroll
        for (int ks = 0; ks < 4; ++ks) {
            afr[ks][0] = qword(rA + 4 * (ks * 8 + tig));
            afr[ks][1] = qword(rB + 4 * (ks * 8 + tig));
            afr[ks][2] = qword(rA + 4 * (ks * 8 + tig + 4));
            afr[ks][3] = qword(rB + 4 * (ks * 8 + tig + 4));
        }
    }
    const int tau0 = g_tau[dir][tBase + gid];
    const int tau1 = g_tau[dir][tBase + gid + 8];
    if (tid < MA) scnt[tid] = 0;
    __syncthreads();

    auto load_tile = [&](int s, int t) {
        uint32_t sb = (uint32_t)__cvta_generic_to_shared(sBd + s * TILE_N * 32);
        const int n0 = segStart + t * TILE_N;
        #pragma unroll
        for (int i = 0; i < 8; ++i) {
            int id = tid + 256 * i;              // 2048 x 16B chunks
            int row = id >> 3;
            int cw = id & 7;
            const void* gp = (const char*)&g_Qrow[bsel][n0 + row][0] + cw * 16;
            uint32_t sw = (uint32_t)((cw * 16) ^ ((row & 7) * 16));
            cp_async16(sb + (uint32_t)(row * 128) + sw, gp);
        }
        cp_commit();
    };

    load_tile(0, 0);

    for (int t = 0; t < TILES_PER_SEG; ++t) {
        cp_wait<0>();
        __syncthreads();
        if (t + 1 < TILES_PER_SEG) load_tile((t + 1) & 1, t + 1);

        const uint32_t (*B)[32] = (const uint32_t (*)[32])(sBd + (t & 1) * TILE_N * 32);
        const int n0 = segStart + t * TILE_N;

        #pragma unroll
        for (int h = 0; h < 2; ++h) {
            const int nw = warpId * 32 + h * 16;

            int c0[4] = {0, 0, 0, 0};
            int c1[4] = {0, 0, 0, 0};
            #pragma unroll
            for (int ks = 0; ks < 4; ++ks) {
                uint32_t b00 = B[nw + gid][(ks * 8 + tig) ^ (gid * 4)];
                uint32_t b01 = B[nw + gid][(ks * 8 + tig + 4) ^ (gid * 4)];
                uint32_t b10 = B[nw + 8 + gid][(ks * 8 + tig) ^ (gid * 4)];
                uint32_t b11 = B[nw + 8 + gid][(ks * 8 + tig + 4) ^ (gid * 4)];
                mma_s8(c0, afr[ks], b00, b01);
                mma_s8(c1, afr[ks], b10, b11);
            }

            #pragma unroll
            for (int nt = 0; nt < 2; ++nt) {
                const int* c = nt ? c1 : c0;
                const int ncol = n0 + nw + nt * 8 + tig * 2;
                int2 s2 = *(const int2*)&g_sumb2[bsel][ncol];
                int k00 = s2.x - 2 * c[0];
                int k01 = s2.y - 2 * c[1];
                int k02 = s2.x - 2 * c[2];
                int k03 = s2.y - 2 * c[3];
                if (k00 < tau0) { int p = atomicAdd(&scnt[gid], 1);     if (p < PCAP) g_pool[dir][tBase + gid][seg][p] = ncol; }
                if (k01 < tau0) { int p = atomicAdd(&scnt[gid], 1);     if (p < PCAP) g_pool[dir][tBase + gid][seg][p] = ncol + 1; }
                if (k02 < tau1) { int p = atomicAdd(&scnt[gid + 8], 1); if (p < PCAP) g_pool[dir][tBase + gid + 8][seg][p] = ncol; }
                if (k03 < tau1) { int p = atomicAdd(&scnt[gid + 8], 1); if (p < PCAP) g_pool[dir][tBase + gid + 8][seg][p] = ncol + 1; }
            }
        }
    }

    __syncthreads();
    if (tid < MA)
        g_cnt[dir][tBase + tid][seg] = min(scnt[tid], PCAP);
}

// ---------------- kernel 4: refine — exact R14 structure ----------------
__global__ __launch_bounds__(256)
void refine_seg_kernel(const float* __restrict__ out1, const float* __restrict__ out2,
                       const int* __restrict__ anchor1, const int* __restrict__ anchor2) {
    const int warpId = threadIdx.x >> 5;
    const int lane = threadIdx.x & 31;
    const int sw = lane >> 3;
    const int sl = lane & 7;
    const int gid = blockIdx.x * 8 + warpId;      // 8192 warps
    const int rseg = gid & 3;
    const int tt = (gid >> 2) & 1023;
    const int dir = gid >> 12;

    const float* Arows = (dir == 0) ? out1 : out2;
    const int* anch = (dir == 0) ? anchor1 : anchor2;
    const float* G = (dir == 0) ? out2 : out1;

    float4 av[4];
    {
        const float4* src = (const float4*)(Arows + anch[tt] * DIM);
        #pragma unroll
        for (int j = 0; j < 4; ++j) av[j] = src[sl + 8 * j];
    }

    const int cnt0 = min(g_cnt[dir][tt][rseg * 2], PCAP);
    const int cnt1 = min(g_cnt[dir][tt][rseg * 2 + 1], PCAP);
    const int total = cnt0 + cnt1;
    const int* pool0 = &g_pool[dir][tt][rseg * 2][0];
    const int* pool1 = &g_pool[dir][tt][rseg * 2 + 1][0];

    float kd[KNEG]; int ki[KNEG];
    #pragma unroll
    for (int k = 0; k < KNEG; ++k) { kd[k] = 3.0e38f; ki[k] = 0x7fffffff; }

    auto load_batch = [&](int base, float4* v, int& idx) {
        int k = base + sw;
        idx = -1;
        if (k < total) {
            int raw = (k < cnt0) ? pool0[k] : pool1[k - cnt0];
            idx = min(raw, NPTS - 1);
            const float4* nr = (const float4*)(G + idx * DIM);
            #pragma unroll
            for (int j = 0; j < 4; ++j) v[j] = nr[sl + 8 * j];
        }
    };

    float4 cv[4];
    int cidx;
    load_batch(0, cv, cidx);

    for (int base = 0; base < total; base += 4) {
        float4 nv[4];
        int nidx = -1;
        if (base + 4 < total) load_batch(base + 4, nv, nidx);

        float dsum = 3.0e38f;
        {
            float p = 0.0f;
            if (cidx >= 0) {
                #pragma unroll
                for (int j = 0; j < 4; ++j) {
                    float4 a = av[j];
                    float4 b = cv[j];
                    p += fabsf(a.x - b.x) + fabsf(a.y - b.y) +
                         fabsf(a.z - b.z) + fabsf(a.w - b.w);
                }
            }
            p += __shfl_xor_sync(0xffffffffu, p, 4);
            p += __shfl_xor_sync(0xffffffffu, p, 2);
            p += __shfl_xor_sync(0xffffffffu, p, 1);
            if (cidx >= 0) dsum = p;
        }

        float thr = __shfl_sync(0xffffffffu, kd[KNEG - 1], 0);
        int   thi = __shfl_sync(0xffffffffu, ki[KNEG - 1], 0);
        bool candp = (sl == 0) && (cidx >= 0) &&
                     (dsum < thr || (dsum == thr && cidx < thi));
        unsigned m = __ballot_sync(0xffffffffu, candp);
        while (m) {
            int src = __ffs(m) - 1; m &= m - 1;
            float d = __shfl_sync(0xffffffffu, dsum, src);
            int  ix = __shfl_sync(0xffffffffu, cidx, src);
            if (lane == 0) {
                bool better = (d < kd[KNEG - 1]) ||
                              (d == kd[KNEG - 1] && ix < ki[KNEG - 1]);
                if (better) {
                    int pos = KNEG - 1;
                    #pragma unroll
                    for (int q = KNEG - 2; q >= 0; --q)
                        if (kd[q] > d || (kd[q] == d && ki[q] > ix)) pos = q;
                    #pragma unroll
                    for (int q = KNEG - 1; q > 0; --q)
                        if (q > pos) { kd[q] = kd[q - 1]; ki[q] = ki[q - 1]; }
                    kd[pos] = d; ki[pos] = ix;
                }
            }
        }

        cidx = nidx;
        #pragma unroll
        for (int j = 0; j < 4; ++j) cv[j] = nv[j];
    }

    if (lane == 0) {
        #pragma unroll
        for (int k = 0; k < KNEG; ++k) {
            g_segd[dir][tt][rseg][k] = kd[k];
            g_segi[dir][tt][rseg][k] = ki[k];
        }
    }
}

// ---------------- kernel 5: merge segments + loss ----------------
__global__ __launch_bounds__(256)
void merge_loss_kernel(const float* __restrict__ out1, const float* __restrict__ out2,
                       const int* __restrict__ anchor1, const int* __restrict__ anchor2) {
    const int warpId = threadIdx.x >> 5;
    const int lane = threadIdx.x & 31;
    const int g = blockIdx.x * 8 + warpId;
    const int dir = g >> 10;
    const int tt = g & 1023;

    const float* r1 = out1 + anchor1[tt] * DIM;
    const float* r2 = out2 + anchor2[tt] * DIM;
    float A = 0.0f;
    #pragma unroll
    for (int j = 0; j < 4; ++j)
        A += fabsf(r1[lane + 32 * j] - r2[lane + 32 * j]);
    A = warp_sum(A);
    const float Dm = A + GAMMA;

    if (lane == 0) {
        float kd[KNEG]; int ki[KNEG];
        #pragma unroll
        for (int k = 0; k < KNEG; ++k) { kd[k] = 3.0e38f; ki[k] = 0x7fffffff; }
        for (int seg = 0; seg < NSEGR; ++seg) {
            #pragma unroll
            for (int k = 0; k < KNEG; ++k) {
                float d = g_segd[dir][tt][seg][k];
                int  ix = g_segi[dir][tt][seg][k];
                bool better = (d < kd[KNEG - 1]) ||
                              (d == kd[KNEG - 1] && ix < ki[KNEG - 1]);
                if (better) {
                    int pos = KNEG - 1;
                    #pragma unroll
                    for (int q = KNEG - 2; q >= 0; --q)
                        if (kd[q] > d || (kd[q] == d && ki[q] > ix)) pos = q;
                    #pragma unroll
                    for (int q = KNEG - 1; q > 0; --q)
                        if (q > pos) { kd[q] = kd[q - 1]; ki[q] = ki[q - 1]; }
                    kd[pos] = d; ki[pos] = ix;
                }
            }
        }
        float lsum = 0.0f;
        #pragma unroll
        for (int k = 0; k < KNEG; ++k) lsum += fmaxf(Dm - kd[k], 0.0f);
        g_partial[g] = lsum;
    }
}

// ---------------- kernel 6: deterministic reduction ----------------
__global__ void reduce_kernel(float* __restrict__ out) {
    __shared__ float sh[1024];
    int t = threadIdx.x;
    sh[t] = g_partial[t] + g_partial[t + 1024];
    __syncthreads();
    #pragma unroll
    for (int s = 512; s > 0; s >>= 1) {
        if (t < s) sh[t] += sh[t + s];
        __syncthreads();
    }
    if (t == 0) out[0] = sh[0] * (1.0f / (float)(TANCH * KNEG));
}

// ---------------- launch ----------------
extern "C" void kernel_launch(void* const* d_in, const int* in_sizes, int n_in,
                              void* d_out, int out_size) {
    const float* out1 = (const float*)d_in[0];
    const float* out2 = (const float*)d_in[1];
    const int* anchor1 = (const int*)d_in[2];
    const int* anchor2 = (const int*)d_in[3];
    float* out = (float*)d_out;

    cudaFuncSetAttribute(mine_mma_kernel,
                         cudaFuncAttributeMaxDynamicSharedMemorySize, MINE_SMEM);

    quant_kernel<<<dim3(N_PAD / 64, 1, 2), 256>>>(out1, out2);                         // #1 (also zeros g_cnt)

    tau_kernel<<<2 * TANCH / 8, 256>>>(out1, out2, anchor1, anchor2);                  // #2

    mine_mma_kernel<<<dim3(TANCH / MA, NSEG, 2), 256, MINE_SMEM>>>(out1, out2, anchor1, anchor2); // #3

    refine_seg_kernel<<<2 * TANCH * NSEGR / 8, 256>>>(out1, out2, anchor1, anchor2);   // #4 <- profiled

    merge_loss_kernel<<<2 * TANCH / 8, 256>>>(out1, out2, anchor1, anchor2);           // #5

    reduce_kernel<<<1, 1024>>>(out);                                                   // #6
}